// round 6
// baseline (speedup 1.0000x reference)
#include <cuda_runtime.h>
#include <cuda_bf16.h>
#include <cstdint>

#define B_MAX 16384

// ---------------- persistent scratch (__device__ globals; no allocations) ----
__device__ float g_w2T[1024 * 64];    // snn_w2 transposed+interleaved: [h][2l]=w2[l][h], [h][2l+1]=w2[l+32][h]
__device__ float g_nnw2T[1024 * 64];  // nn_w2 transposed: [h][o]
__device__ float g_fcT[1600 * 256];   // cnn_fc_w transposed: [k][o]
__device__ float g_combT[384 * 64];   // comb_w transposed: [c][o]
__device__ float g_snn[B_MAX * 64];
__device__ float g_nn[B_MAX * 64];
__device__ float g_cnn[B_MAX * 256];

// ---------------- weight transpose ------------------------------------------
__global__ void prep_kernel(const float* __restrict__ snn_w2,
                            const float* __restrict__ nn_w2,
                            const float* __restrict__ fc_w,
                            const float* __restrict__ comb_w) {
    int i = blockIdx.x * blockDim.x + threadIdx.x;
    if (i < 1024 * 64) {
        int h = i >> 6, q = i & 63;
        int o = (q >> 1) + ((q & 1) << 5);      // paired layout for float2 loads
        g_w2T[i] = snn_w2[o * 1024 + h];
    }
    if (i < 1024 * 64) {
        int h = i >> 6, o = i & 63;
        g_nnw2T[i] = nn_w2[o * 1024 + h];
    }
    if (i < 1600 * 256) {
        int k = i >> 8, o = i & 255;
        g_fcT[i] = fc_w[o * 1600 + k];
    }
    if (i < 384 * 64) {
        int c = i >> 6, o = i & 63;
        g_combT[i] = comb_w[o * 384 + c];
    }
}

// ---------------- SNN: one block per batch row -------------------------------
__global__ __launch_bounds__(256) void snn_kernel(const float* __restrict__ x,
                                                  const float* __restrict__ w1,
                                                  const float* __restrict__ b1,
                                                  const float* __restrict__ b2,
                                                  int B) {
    __shared__ unsigned s_spk[100 * 32];   // [t][word] layer-1 spike bits
    __shared__ float    s_cur2[100 * 64];  // [t][o]
    __shared__ float    s_feats[5];

    int b   = blockIdx.x;
    int tid = threadIdx.x;
    int wid = tid >> 5;
    int l   = tid & 31;

    if (tid < 5) s_feats[tid] = x[b * 105 + tid];
    __syncthreads();

    float f0 = s_feats[0], f1 = s_feats[1], f2 = s_feats[2],
          f3 = s_feats[3], f4 = s_feats[4];

    // phase 1: layer-1 LIF dynamics, spikes -> ballot bitmask
    for (int p = 0; p < 4; p++) {
        int h = p * 256 + wid * 32 + l;
        const float* wr = w1 + h * 5;
        float c = b1[h] + f0 * wr[0] + f1 * wr[1] + f2 * wr[2] + f3 * wr[3] + f4 * wr[4];
        float mem = 0.f, sp = 0.f;
        #pragma unroll 4
        for (int t = 0; t < 100; t++) {
            mem = __fmaf_rn(0.95f, mem, c) - sp;   // beta*mem + cur1 - spk_prev*THR
            bool s = mem > 1.0f;                   // atan_spike(mem - THR) fwd = (x>0)
            unsigned m = __ballot_sync(0xffffffffu, s);
            if (l == 0) s_spk[t * 32 + p * 8 + wid] = m;
            sp = s ? 1.0f : 0.0f;
        }
    }
    __syncthreads();

    // phase 2: sparse cur2[t][o] = b2[o] + sum_{spiking h} w2[o][h]
    const float2* w2p = (const float2*)g_w2T;      // [h][32] pairs (o, o+32)
    for (int t = wid; t < 100; t += 8) {
        float a0 = b2[l], a1 = b2[l + 32];
        #pragma unroll 4
        for (int w = 0; w < 32; w++) {
            unsigned bits = s_spk[t * 32 + w];
            while (bits) {
                int j = __ffs(bits) - 1;
                bits &= bits - 1;
                float2 v = w2p[(unsigned)(w * 32 + j) * 32 + l];
                a0 += v.x;
                a1 += v.y;
            }
        }
        s_cur2[t * 64 + l]      = a0;
        s_cur2[t * 64 + 32 + l] = a1;
    }
    __syncthreads();

    // phase 3: layer-2 LIF scan + mean
    if (tid < 64) {
        float mem = 0.f, sp = 0.f, sum = 0.f;
        #pragma unroll 4
        for (int t = 0; t < 100; t++) {
            mem = __fmaf_rn(0.95f, mem, s_cur2[t * 64 + tid]) - sp;
            bool s = mem > 1.0f;
            sp = s ? 1.0f : 0.0f;
            sum += sp;
        }
        g_snn[b * 64 + tid] = sum * 0.01f;
    }
}

// ---------------- plain MLP: 8 rows per block --------------------------------
__global__ __launch_bounds__(256) void nn_kernel(const float* __restrict__ x,
                                                 const float* __restrict__ w1,
                                                 const float* __restrict__ b1,
                                                 const float* __restrict__ b2,
                                                 int B) {
    __shared__ float s_h[8 * 1024];   // [r][h]
    __shared__ float s_f[8][5];

    int b0  = blockIdx.x * 8;
    int tid = threadIdx.x;

    if (tid < 40) {
        int r = tid / 5, k = tid % 5;
        s_f[r][k] = x[(b0 + r) * 105 + k];
    }
    __syncthreads();

    // hidden layer
    for (int j = 0; j < 4; j++) {
        int h = tid + 256 * j;
        const float* wr = w1 + h * 5;
        float w0 = wr[0], w1v = wr[1], w2v = wr[2], w3 = wr[3], w4 = wr[4];
        float bb = b1[h];
        #pragma unroll
        for (int r = 0; r < 8; r++) {
            float v = bb + s_f[r][0] * w0 + s_f[r][1] * w1v + s_f[r][2] * w2v +
                      s_f[r][3] * w3 + s_f[r][4] * w4;
            s_h[r * 1024 + h] = v > 0.f ? v : 0.f;
        }
    }
    __syncthreads();

    // output layer: 8 rows x 64 outputs, 2 rows per thread
    int o  = tid & 63;
    int rg = tid >> 6;             // 0..3 -> rows 2rg, 2rg+1
    float a0 = 0.f, a1 = 0.f;
    const float* h0 = s_h + (rg * 2) * 1024;
    const float* h1 = s_h + (rg * 2 + 1) * 1024;
    for (int h = 0; h < 1024; h++) {
        float w = g_nnw2T[h * 64 + o];
        a0 += w * h0[h];
        a1 += w * h1[h];
    }
    float bo = b2[o];
    g_nn[(b0 + rg * 2) * 64 + o]     = a0 + bo;
    g_nn[(b0 + rg * 2 + 1) * 64 + o] = a1 + bo;
}

// ---------------- CNN: 16 rows per block, f32x2 FC ---------------------------
#define CNN_SMEM_BYTES ((25600 + 16 * 102) * 4)

__global__ __launch_bounds__(256) void cnn_kernel(const float* __restrict__ x,
                                                  const float* __restrict__ cw,
                                                  const float* __restrict__ cb,
                                                  const float* __restrict__ fcb,
                                                  int B) {
    extern __shared__ float sm[];
    float* s_p    = sm;            // pooled features, transposed: [k=ch*50+j][r] (1600 x 16)
    float* s_wave = sm + 25600;    // [r][102] with zero pad at 0 and 101

    __shared__ float s_cw[96];
    __shared__ float s_cb[32];

    int b0  = blockIdx.x * 16;
    int tid = threadIdx.x;

    if (tid < 96) s_cw[tid] = cw[tid];
    if (tid < 32) s_cb[tid] = cb[tid];
    for (int i = tid; i < 16 * 102; i += 256) {
        int r = i / 102, q = i % 102;
        float v = 0.f;
        if (q >= 1 && q <= 100) v = x[(b0 + r) * 105 + 4 + q];   // q=1 -> col 5
        s_wave[i] = v;
    }
    __syncthreads();

    // conv(pad=1,k=3) + bias + relu + maxpool2
    for (int i = tid; i < 25600; i += 256) {
        int r   = i & 15;
        int pos = i >> 4;            // ch*50 + j
        int ch  = pos / 50;
        int j   = pos - ch * 50;
        const float* wv = s_wave + r * 102 + 2 * j;
        float w0 = s_cw[ch * 3], w1 = s_cw[ch * 3 + 1], w2 = s_cw[ch * 3 + 2];
        float bb = s_cb[ch];
        float c0 = bb + wv[0] * w0 + wv[1] * w1 + wv[2] * w2;   // out pos 2j
        float c1 = bb + wv[1] * w0 + wv[2] * w1 + wv[3] * w2;   // out pos 2j+1
        float m = fmaxf(c0, c1);
        s_p[pos * 16 + r] = m > 0.f ? m : 0.f;
    }
    __syncthreads();

    // FC 1600 -> 256: each thread owns output o for all 16 rows (8 f32x2 accs)
    int o = tid;
    unsigned long long a[8];
    #pragma unroll
    for (int q = 0; q < 8; q++) a[q] = 0ull;   // bit pattern of (0.f, 0.f)

    for (int k = 0; k < 1600; k++) {
        float w = g_fcT[k * 256 + o];
        unsigned long long ww;
        asm("mov.b64 %0, {%1, %1};" : "=l"(ww) : "r"(__float_as_uint(w)));
        const unsigned long long* row = (const unsigned long long*)(s_p + k * 16);
        #pragma unroll
        for (int q = 0; q < 8; q++) {
            unsigned long long v = row[q];
            asm("fma.rn.f32x2 %0, %1, %2, %0;" : "+l"(a[q]) : "l"(v), "l"(ww));
        }
    }
    float fb = fcb[o];
    #pragma unroll
    for (int q = 0; q < 8; q++) {
        float lo = __uint_as_float((unsigned)(a[q] & 0xffffffffull));
        float hi = __uint_as_float((unsigned)(a[q] >> 32));
        g_cnn[(b0 + 2 * q) * 256 + o]     = lo + fb;
        g_cnn[(b0 + 2 * q + 1) * 256 + o] = hi + fb;
    }
}

// ---------------- combiner ----------------------------------------------------
__global__ __launch_bounds__(256) void comb_kernel(const float* __restrict__ cbias,
                                                   float* __restrict__ out,
                                                   int B) {
    __shared__ float s_c[16 * 384];   // [r][c]
    int b0  = blockIdx.x * 16;
    int tid = threadIdx.x;

    for (int i = tid; i < 16 * 64; i += 256) {
        int r = i >> 6, o = i & 63;
        s_c[r * 384 + o]      = g_snn[(b0 + r) * 64 + o];
        s_c[r * 384 + 64 + o] = g_nn[(b0 + r) * 64 + o];
    }
    for (int i = tid; i < 16 * 256; i += 256) {
        int r = i >> 8, o = i & 255;
        s_c[r * 384 + 128 + o] = g_cnn[(b0 + r) * 256 + o];
    }
    __syncthreads();

    int o  = tid & 63;
    int rg = tid >> 6;   // 4 rows each
    float a[4] = {0.f, 0.f, 0.f, 0.f};
    for (int c = 0; c < 384; c++) {
        float w = g_combT[c * 64 + o];
        const float* pr = s_c + (rg * 4) * 384 + c;
        a[0] += w * pr[0];
        a[1] += w * pr[384];
        a[2] += w * pr[2 * 384];
        a[3] += w * pr[3 * 384];
    }
    float bo = cbias[o];
    #pragma unroll
    for (int q = 0; q < 4; q++)
        out[(b0 + rg * 4 + q) * 64 + o] = a[q] + bo;
}

// ---------------- launch -------------------------------------------------------
extern "C" void kernel_launch(void* const* d_in, const int* in_sizes, int n_in,
                              void* d_out, int out_size) {
    const float* x      = (const float*)d_in[0];
    const float* snn_w1 = (const float*)d_in[1];
    const float* snn_b1 = (const float*)d_in[2];
    const float* snn_w2 = (const float*)d_in[3];
    const float* snn_b2 = (const float*)d_in[4];
    const float* nn_w1  = (const float*)d_in[5];
    const float* nn_b1  = (const float*)d_in[6];
    const float* nn_w2  = (const float*)d_in[7];
    const float* nn_b2  = (const float*)d_in[8];
    const float* conv_w = (const float*)d_in[9];
    const float* conv_b = (const float*)d_in[10];
    const float* fc_w   = (const float*)d_in[11];
    const float* fc_b   = (const float*)d_in[12];
    const float* comb_w = (const float*)d_in[13];
    const float* comb_b = (const float*)d_in[14];

    int B = in_sizes[0] / 105;

    cudaFuncSetAttribute(cnn_kernel, cudaFuncAttributeMaxDynamicSharedMemorySize,
                         CNN_SMEM_BYTES);

    prep_kernel<<<1600, 256>>>(snn_w2, nn_w2, fc_w, comb_w);
    snn_kernel<<<B, 256>>>(x, snn_w1, snn_b1, snn_b2, B);
    nn_kernel<<<B / 8, 256>>>(x, nn_w1, nn_b1, nn_b2, B);
    cnn_kernel<<<B / 16, 256, CNN_SMEM_BYTES>>>(x, conv_w, conv_b, fc_b, B);
    comb_kernel<<<B / 16, 256>>>(comb_b, (float*)d_out, B);
}

// round 7
// speedup vs baseline: 1.4382x; 1.4382x over previous
#include <cuda_runtime.h>
#include <cuda_bf16.h>
#include <cstdint>

#define B_MAX 16384

// ---------------- persistent scratch (__device__ globals; no allocations) ----
__device__ float g_w2T[1024 * 64];    // snn_w2 transposed: [h][o] = w2[o][h]
__device__ float g_nnw2T[1024 * 64];  // nn_w2 transposed: [h][o]
__device__ float g_fcT[1600 * 256];   // cnn_fc_w transposed: [k][o]
__device__ float g_combT[384 * 64];   // comb_w transposed: [c][o]
__device__ float g_snn[B_MAX * 64];
__device__ float g_nn[B_MAX * 64];
__device__ float g_cnn[B_MAX * 256];

// ---------------- weight transpose ------------------------------------------
__global__ void prep_kernel(const float* __restrict__ snn_w2,
                            const float* __restrict__ nn_w2,
                            const float* __restrict__ fc_w,
                            const float* __restrict__ comb_w) {
    int i = blockIdx.x * blockDim.x + threadIdx.x;
    if (i < 1024 * 64) {
        int h = i >> 6, o = i & 63;
        g_w2T[i]   = snn_w2[o * 1024 + h];
        g_nnw2T[i] = nn_w2[o * 1024 + h];
    }
    if (i < 1600 * 256) {
        int k = i >> 8, o = i & 255;
        g_fcT[i] = fc_w[o * 1600 + k];
    }
    if (i < 384 * 64) {
        int c = i >> 6, o = i & 63;
        g_combT[i] = comb_w[o * 384 + c];
    }
}

// ---------------- SNN: one block (1024 thr) per batch row --------------------
// Compaction: neurons with cur1 <= ~0.05 can never spike (mem asymptote 20*c <= 1),
// so only ~33% of neurons run dynamics. Phase 2 gathers w2 rows per spike with
// float2 loads; 2 blocks/SM keeps ~138KB of L1 for the 256KB w2T working set.
__global__ __launch_bounds__(1024, 2) void snn_kernel(const float* __restrict__ x,
                                                      const float* __restrict__ w1,
                                                      const float* __restrict__ b1,
                                                      const float* __restrict__ b2,
                                                      int B) {
    __shared__ float          s_cur2[100 * 64];  // [t][o]
    __shared__ unsigned       s_masks[100 * 32]; // [t][chunk] spike bits (compact space)
    __shared__ unsigned short s_idx[1024];       // compact -> neuron index
    __shared__ float          s_cval[1024];      // compact -> drive c
    __shared__ unsigned       s_gm[32];
    __shared__ int            s_wbase[32];
    __shared__ int            s_nact;
    __shared__ float          s_feats[5];

    int b   = blockIdx.x;
    int tid = threadIdx.x;
    int wid = tid >> 5;
    int l   = tid & 31;

    if (tid < 5) s_feats[tid] = x[b * 105 + tid];
    __syncthreads();

    // ---- drive c per neuron + compaction (deterministic prefix) ----
    float f0 = s_feats[0], f1 = s_feats[1], f2 = s_feats[2],
          f3 = s_feats[3], f4 = s_feats[4];
    const float* wr = w1 + tid * 5;
    float c = b1[tid] + f0 * wr[0] + f1 * wr[1] + f2 * wr[2] + f3 * wr[3] + f4 * wr[4];
    bool act = c > 0.049995f;   // inclusion margin; excluded neurons provably silent
    unsigned gm = __ballot_sync(0xffffffffu, act);
    if (l == 0) s_gm[wid] = gm;
    __syncthreads();
    if (tid < 32) {
        int cnt = __popc(s_gm[tid]);
        int incl = cnt;
        #pragma unroll
        for (int d = 1; d < 32; d <<= 1) {
            int v = __shfl_up_sync(0xffffffffu, incl, d);
            if (tid >= d) incl += v;
        }
        s_wbase[tid] = incl - cnt;
        if (tid == 31) s_nact = incl;
    }
    __syncthreads();
    if (act) {
        int pos = s_wbase[wid] + __popc(gm & ((1u << l) - 1u));
        s_idx[pos]  = (unsigned short)tid;
        s_cval[pos] = c;
    }
    __syncthreads();

    int nact   = s_nact;
    int chunks = (nact + 31) >> 5;

    // ---- phase 1: LIF dynamics for active neurons only ----
    for (int ci = wid; ci < chunks; ci += 32) {
        int i = ci * 32 + l;
        float cc = (i < nact) ? s_cval[i] : -1e30f;
        float mem = 0.f, sp = 0.f;
        #pragma unroll 4
        for (int t = 0; t < 100; t++) {
            mem = __fmaf_rn(0.95f, mem, cc) - sp;
            bool s = mem > 1.0f;
            unsigned m = __ballot_sync(0xffffffffu, s);
            if (l == 0) s_masks[t * 32 + ci] = m;
            sp = s ? 1.0f : 0.0f;
        }
    }
    __syncthreads();

    // ---- phase 2: sparse cur2 gather, lane l owns outputs (2l, 2l+1) ----
    const float2* w2p = (const float2*)g_w2T;   // [h][32] float2
    float b20 = b2[2 * l], b21 = b2[2 * l + 1];
    for (int t = wid; t < 100; t += 32) {
        float a0 = b20, a1 = b21;
        for (int ci = 0; ci < chunks; ci++) {
            unsigned m = s_masks[t * 32 + ci];
            while (m) {
                int j = __ffs(m) - 1;
                m &= m - 1;
                int hh = s_idx[ci * 32 + j];
                float2 v = w2p[(unsigned)hh * 32 + l];
                a0 += v.x;
                a1 += v.y;
            }
        }
        ((float2*)s_cur2)[t * 32 + l] = make_float2(a0, a1);
    }
    __syncthreads();

    // ---- phase 3: layer-2 LIF scan + mean ----
    if (tid < 64) {
        float mem = 0.f, sp = 0.f, sum = 0.f;
        #pragma unroll 4
        for (int t = 0; t < 100; t++) {
            mem = __fmaf_rn(0.95f, mem, s_cur2[t * 64 + tid]) - sp;
            bool s = mem > 1.0f;
            sp = s ? 1.0f : 0.0f;
            sum += sp;
        }
        g_snn[b * 64 + tid] = sum * 0.01f;
    }
}

// ---------------- plain MLP: 8 rows per block --------------------------------
__global__ __launch_bounds__(256) void nn_kernel(const float* __restrict__ x,
                                                 const float* __restrict__ w1,
                                                 const float* __restrict__ b1,
                                                 const float* __restrict__ b2,
                                                 int B) {
    __shared__ float s_h[8 * 1024];   // [r][h]
    __shared__ float s_f[8][5];

    int b0  = blockIdx.x * 8;
    int tid = threadIdx.x;

    if (tid < 40) {
        int r = tid / 5, k = tid % 5;
        s_f[r][k] = x[(b0 + r) * 105 + k];
    }
    __syncthreads();

    for (int j = 0; j < 4; j++) {
        int h = tid + 256 * j;
        const float* wr = w1 + h * 5;
        float w0 = wr[0], w1v = wr[1], w2v = wr[2], w3 = wr[3], w4 = wr[4];
        float bb = b1[h];
        #pragma unroll
        for (int r = 0; r < 8; r++) {
            float v = bb + s_f[r][0] * w0 + s_f[r][1] * w1v + s_f[r][2] * w2v +
                      s_f[r][3] * w3 + s_f[r][4] * w4;
            s_h[r * 1024 + h] = v > 0.f ? v : 0.f;
        }
    }
    __syncthreads();

    int o  = tid & 63;
    int rg = tid >> 6;
    float a0 = 0.f, a1 = 0.f;
    const float* h0 = s_h + (rg * 2) * 1024;
    const float* h1 = s_h + (rg * 2 + 1) * 1024;
    for (int h = 0; h < 1024; h++) {
        float w = g_nnw2T[h * 64 + o];
        a0 += w * h0[h];
        a1 += w * h1[h];
    }
    float bo = b2[o];
    g_nn[(b0 + rg * 2) * 64 + o]     = a0 + bo;
    g_nn[(b0 + rg * 2 + 1) * 64 + o] = a1 + bo;
}

// ---------------- CNN: 16 rows/block, 512 thr (k-split), f32x2 FC ------------
#define CNN_SMEM_BYTES ((25600 + 16 * 102) * 4)

__global__ __launch_bounds__(512, 2) void cnn_kernel(const float* __restrict__ x,
                                                     const float* __restrict__ cw,
                                                     const float* __restrict__ cb,
                                                     const float* __restrict__ fcb,
                                                     int B) {
    extern __shared__ float sm[];
    float* s_p    = sm;            // pooled, transposed: [k=ch*50+j][r] (1600 x 16)
    float* s_wave = sm + 25600;    // [r][102] zero-padded

    __shared__ float s_cw[96];
    __shared__ float s_cb[32];

    int b0  = blockIdx.x * 16;
    int tid = threadIdx.x;

    if (tid < 96) s_cw[tid] = cw[tid];
    if (tid < 32) s_cb[tid] = cb[tid];
    for (int i = tid; i < 16 * 102; i += 512) {
        int r = i / 102, q = i % 102;
        float v = 0.f;
        if (q >= 1 && q <= 100) v = x[(b0 + r) * 105 + 4 + q];
        s_wave[i] = v;
    }
    __syncthreads();

    // conv(pad=1,k=3) + bias + relu + maxpool2
    for (int i = tid; i < 25600; i += 512) {
        int r   = i & 15;
        int pos = i >> 4;
        int ch  = pos / 50;
        int j   = pos - ch * 50;
        const float* wv = s_wave + r * 102 + 2 * j;
        float w0 = s_cw[ch * 3], w1 = s_cw[ch * 3 + 1], w2 = s_cw[ch * 3 + 2];
        float bb = s_cb[ch];
        float c0 = bb + wv[0] * w0 + wv[1] * w1 + wv[2] * w2;
        float c1 = bb + wv[1] * w0 + wv[2] * w1 + wv[3] * w2;
        float m = fmaxf(c0, c1);
        s_p[pos * 16 + r] = m > 0.f ? m : 0.f;
    }
    __syncthreads();

    // FC 1600 -> 256: thread = (output o, k-half kh); 8 f32x2 accumulators
    int o  = tid & 255;
    int kh = tid >> 8;                 // 0: k 0..799, 1: k 800..1599
    unsigned long long a[8];
    #pragma unroll
    for (int q = 0; q < 8; q++) a[q] = 0ull;

    int kbeg = kh * 800;
    const float* fp = g_fcT + (size_t)kbeg * 256 + o;
    const ulonglong2* rp = (const ulonglong2*)s_p + kbeg * 4;   // 4 x 16B per k

    for (int kk = 0; kk < 800; kk += 4) {
        float w0 = fp[0], w1 = fp[256], w2 = fp[512], w3 = fp[768];
        fp += 1024;
        unsigned long long W[4];
        asm("mov.b64 %0, {%1, %1};" : "=l"(W[0]) : "r"(__float_as_uint(w0)));
        asm("mov.b64 %0, {%1, %1};" : "=l"(W[1]) : "r"(__float_as_uint(w1)));
        asm("mov.b64 %0, {%1, %1};" : "=l"(W[2]) : "r"(__float_as_uint(w2)));
        asm("mov.b64 %0, {%1, %1};" : "=l"(W[3]) : "r"(__float_as_uint(w3)));
        #pragma unroll
        for (int u = 0; u < 4; u++) {
            #pragma unroll
            for (int m2 = 0; m2 < 4; m2++) {
                ulonglong2 v = rp[u * 4 + m2];
                asm("fma.rn.f32x2 %0, %1, %2, %0;" : "+l"(a[2 * m2])     : "l"(v.x), "l"(W[u]));
                asm("fma.rn.f32x2 %0, %1, %2, %0;" : "+l"(a[2 * m2 + 1]) : "l"(v.y), "l"(W[u]));
            }
        }
        rp += 16;
    }

    // combine halves through g_cnn (visible across __syncthreads within block)
    if (kh == 1) {
        #pragma unroll
        for (int q = 0; q < 8; q++) {
            float lo = __uint_as_float((unsigned)(a[q] & 0xffffffffull));
            float hi = __uint_as_float((unsigned)(a[q] >> 32));
            g_cnn[(b0 + 2 * q) * 256 + o]     = lo;
            g_cnn[(b0 + 2 * q + 1) * 256 + o] = hi;
        }
    }
    __syncthreads();
    if (kh == 0) {
        float fb = fcb[o];
        #pragma unroll
        for (int q = 0; q < 8; q++) {
            float lo = __uint_as_float((unsigned)(a[q] & 0xffffffffull));
            float hi = __uint_as_float((unsigned)(a[q] >> 32));
            int r0 = (b0 + 2 * q) * 256 + o;
            int r1 = (b0 + 2 * q + 1) * 256 + o;
            g_cnn[r0] = lo + fb + g_cnn[r0];
            g_cnn[r1] = hi + fb + g_cnn[r1];
        }
    }
}

// ---------------- combiner ----------------------------------------------------
__global__ __launch_bounds__(256) void comb_kernel(const float* __restrict__ cbias,
                                                   float* __restrict__ out,
                                                   int B) {
    __shared__ float s_c[16 * 384];   // [r][c]
    int b0  = blockIdx.x * 16;
    int tid = threadIdx.x;

    for (int i = tid; i < 16 * 64; i += 256) {
        int r = i >> 6, o = i & 63;
        s_c[r * 384 + o]      = g_snn[(b0 + r) * 64 + o];
        s_c[r * 384 + 64 + o] = g_nn[(b0 + r) * 64 + o];
    }
    for (int i = tid; i < 16 * 256; i += 256) {
        int r = i >> 8, o = i & 255;
        s_c[r * 384 + 128 + o] = g_cnn[(b0 + r) * 256 + o];
    }
    __syncthreads();

    int o  = tid & 63;
    int rg = tid >> 6;
    float a[4] = {0.f, 0.f, 0.f, 0.f};
    for (int c = 0; c < 384; c++) {
        float w = g_combT[c * 64 + o];
        const float* pr = s_c + (rg * 4) * 384 + c;
        a[0] += w * pr[0];
        a[1] += w * pr[384];
        a[2] += w * pr[2 * 384];
        a[3] += w * pr[3 * 384];
    }
    float bo = cbias[o];
    #pragma unroll
    for (int q = 0; q < 4; q++)
        out[(b0 + rg * 4 + q) * 64 + o] = a[q] + bo;
}

// ---------------- launch -------------------------------------------------------
extern "C" void kernel_launch(void* const* d_in, const int* in_sizes, int n_in,
                              void* d_out, int out_size) {
    const float* x      = (const float*)d_in[0];
    const float* snn_w1 = (const float*)d_in[1];
    const float* snn_b1 = (const float*)d_in[2];
    const float* snn_w2 = (const float*)d_in[3];
    const float* snn_b2 = (const float*)d_in[4];
    const float* nn_w1  = (const float*)d_in[5];
    const float* nn_b1  = (const float*)d_in[6];
    const float* nn_w2  = (const float*)d_in[7];
    const float* nn_b2  = (const float*)d_in[8];
    const float* conv_w = (const float*)d_in[9];
    const float* conv_b = (const float*)d_in[10];
    const float* fc_w   = (const float*)d_in[11];
    const float* fc_b   = (const float*)d_in[12];
    const float* comb_w = (const float*)d_in[13];
    const float* comb_b = (const float*)d_in[14];

    int B = in_sizes[0] / 105;

    cudaFuncSetAttribute(cnn_kernel, cudaFuncAttributeMaxDynamicSharedMemorySize,
                         CNN_SMEM_BYTES);

    prep_kernel<<<1600, 256>>>(snn_w2, nn_w2, fc_w, comb_w);
    snn_kernel<<<B, 1024>>>(x, snn_w1, snn_b1, snn_b2, B);
    nn_kernel<<<B / 8, 256>>>(x, nn_w1, nn_b1, nn_b2, B);
    cnn_kernel<<<B / 16, 512, CNN_SMEM_BYTES>>>(x, conv_w, conv_b, fc_b, B);
    comb_kernel<<<B / 16, 256>>>(comb_b, (float*)d_out, B);
}

// round 8
// speedup vs baseline: 1.8083x; 1.2574x over previous
#include <cuda_runtime.h>
#include <cuda_bf16.h>
#include <cstdint>

#define B_MAX 16384

// ---------------- persistent scratch (__device__ globals; no allocations) ----
__device__ int   g_w2I[1024 * 64];    // snn_w2 transposed+paired, fixed-point 2^24:
                                      //   [h][2l] = w2[2l][h], [h][2l+1] = w2[2l+1][h]
__device__ float g_nnw2T[1024 * 64];  // nn_w2 transposed: [h][o]
__device__ float g_fcT[1600 * 256];   // cnn_fc_w transposed: [k][o]
__device__ float g_combT[384 * 64];   // comb_w transposed: [c][o]
__device__ float g_snn[B_MAX * 64];
__device__ float g_nn[B_MAX * 64];
__device__ float g_cnn[B_MAX * 256];

#define W2_SCALE   16777216.0f        // 2^24
#define W2_INVSCALE 5.9604645e-8f     // 2^-24

// ---------------- weight transpose ------------------------------------------
__global__ void prep_kernel(const float* __restrict__ snn_w2,
                            const float* __restrict__ nn_w2,
                            const float* __restrict__ fc_w,
                            const float* __restrict__ comb_w) {
    int i = blockIdx.x * blockDim.x + threadIdx.x;
    if (i < 1024 * 64) {
        int h = i >> 6, o = i & 63;
        g_w2I[i]   = __float2int_rn(snn_w2[o * 1024 + h] * W2_SCALE);
        g_nnw2T[i] = nn_w2[o * 1024 + h];
    }
    if (i < 1600 * 256) {
        int k = i >> 8, o = i & 255;
        g_fcT[i] = fc_w[o * 1600 + k];
    }
    if (i < 384 * 64) {
        int c = i >> 6, o = i & 63;
        g_combT[i] = comb_w[o * 384 + c];
    }
}

// ---------------- SNN: one block (1024 thr) per batch row --------------------
// Compaction: neurons with drive c <= ~0.05 provably never spike (mem asymptote
// 20c <= 1). Phase 1: each active neuron's thread builds its own 100-bit spike
// train in registers. Phase 2 (neuron-major): each warp loads a neuron's w2 row
// ONCE and scatters it into per-timestep accumulators via integer shared
// atomics (2^24 fixed point -> order-independent, deterministic). This cuts w2
// traffic ~7x vs spike-major gathering.
__global__ __launch_bounds__(1024, 2) void snn_kernel(const float* __restrict__ x,
                                                      const float* __restrict__ w1,
                                                      const float* __restrict__ b1,
                                                      const float* __restrict__ b2,
                                                      int B) {
    __shared__ int            s_acc[100 * 64];   // [t][o] fixed-point cur2 accum
    __shared__ uint4          s_train[1024];     // per-active-neuron spike bits
    __shared__ unsigned short s_idx[1024];       // compact -> neuron index
    __shared__ float          s_cval[1024];      // compact -> drive c
    __shared__ unsigned       s_gm[32];
    __shared__ int            s_wbase[32];
    __shared__ int            s_nact;
    __shared__ float          s_feats[5];

    int b   = blockIdx.x;
    int tid = threadIdx.x;
    int wid = tid >> 5;
    int l   = tid & 31;

    if (tid < 5) s_feats[tid] = x[b * 105 + tid];
    __syncthreads();

    // ---- drive c per neuron + compaction (deterministic prefix) ----
    float f0 = s_feats[0], f1 = s_feats[1], f2 = s_feats[2],
          f3 = s_feats[3], f4 = s_feats[4];
    const float* wr = w1 + tid * 5;
    float c = b1[tid] + f0 * wr[0] + f1 * wr[1] + f2 * wr[2] + f3 * wr[3] + f4 * wr[4];
    bool act = c > 0.049995f;   // inclusion margin; excluded neurons provably silent
    unsigned gm = __ballot_sync(0xffffffffu, act);
    if (l == 0) s_gm[wid] = gm;

    // zero the cur2 accumulators while compaction data settles
    #pragma unroll
    for (int i = tid; i < 6400; i += 1024) s_acc[i] = 0;
    __syncthreads();

    if (tid < 32) {
        int cnt = __popc(s_gm[tid]);
        int incl = cnt;
        #pragma unroll
        for (int d = 1; d < 32; d <<= 1) {
            int v = __shfl_up_sync(0xffffffffu, incl, d);
            if (tid >= d) incl += v;
        }
        s_wbase[tid] = incl - cnt;
        if (tid == 31) s_nact = incl;
    }
    __syncthreads();
    if (act) {
        int pos = s_wbase[wid] + __popc(gm & ((1u << l) - 1u));
        s_idx[pos]  = (unsigned short)tid;
        s_cval[pos] = c;
    }
    __syncthreads();

    int nact = s_nact;

    // ---- phase 1: LIF dynamics; each active neuron builds its spike train ----
    if (tid < nact) {
        float cc = s_cval[tid];
        float mem = 0.f, sp = 0.f;
        unsigned tr0 = 0, tr1 = 0, tr2 = 0, tr3 = 0;
        #pragma unroll
        for (int u = 0; u < 32; u++) {
            mem = __fmaf_rn(0.95f, mem, cc) - sp;
            bool s = mem > 1.0f; sp = s ? 1.0f : 0.0f;
            tr0 |= ((unsigned)s) << u;
        }
        #pragma unroll
        for (int u = 0; u < 32; u++) {
            mem = __fmaf_rn(0.95f, mem, cc) - sp;
            bool s = mem > 1.0f; sp = s ? 1.0f : 0.0f;
            tr1 |= ((unsigned)s) << u;
        }
        #pragma unroll
        for (int u = 0; u < 32; u++) {
            mem = __fmaf_rn(0.95f, mem, cc) - sp;
            bool s = mem > 1.0f; sp = s ? 1.0f : 0.0f;
            tr2 |= ((unsigned)s) << u;
        }
        #pragma unroll
        for (int u = 0; u < 4; u++) {
            mem = __fmaf_rn(0.95f, mem, cc) - sp;
            bool s = mem > 1.0f; sp = s ? 1.0f : 0.0f;
            tr3 |= ((unsigned)s) << u;
        }
        s_train[tid] = make_uint4(tr0, tr1, tr2, tr3);
    }
    __syncthreads();

    // ---- phase 2: neuron-major scatter; lane l owns outputs (2l, 2l+1) ----
    const int2* w2p = (const int2*)g_w2I;   // [h][32] int2 pairs
    for (int i = wid; i < nact; i += 32) {
        int2 v  = w2p[(unsigned)s_idx[i] * 32 + l];   // one 256B row load per neuron
        uint4 tr = s_train[i];                        // broadcast LDS.128
        unsigned m;
        m = tr.x;
        while (m) {
            int t = __ffs(m) - 1; m &= m - 1;
            atomicAdd(&s_acc[t * 64 + 2 * l],     v.x);
            atomicAdd(&s_acc[t * 64 + 2 * l + 1], v.y);
        }
        m = tr.y;
        while (m) {
            int t = 32 + __ffs(m) - 1; m &= m - 1;
            atomicAdd(&s_acc[t * 64 + 2 * l],     v.x);
            atomicAdd(&s_acc[t * 64 + 2 * l + 1], v.y);
        }
        m = tr.z;
        while (m) {
            int t = 64 + __ffs(m) - 1; m &= m - 1;
            atomicAdd(&s_acc[t * 64 + 2 * l],     v.x);
            atomicAdd(&s_acc[t * 64 + 2 * l + 1], v.y);
        }
        m = tr.w;
        while (m) {
            int t = 96 + __ffs(m) - 1; m &= m - 1;
            atomicAdd(&s_acc[t * 64 + 2 * l],     v.x);
            atomicAdd(&s_acc[t * 64 + 2 * l + 1], v.y);
        }
    }
    __syncthreads();

    // ---- phase 3: layer-2 LIF scan + mean ----
    if (tid < 64) {
        float b2o = b2[tid];
        float mem = 0.f, sp = 0.f, sum = 0.f;
        #pragma unroll 4
        for (int t = 0; t < 100; t++) {
            float cur = __fmaf_rn((float)s_acc[t * 64 + tid], W2_INVSCALE, b2o);
            mem = __fmaf_rn(0.95f, mem, cur) - sp;
            bool s = mem > 1.0f;
            sp = s ? 1.0f : 0.0f;
            sum += sp;
        }
        g_snn[b * 64 + tid] = sum * 0.01f;
    }
}

// ---------------- plain MLP: 8 rows per block --------------------------------
__global__ __launch_bounds__(256) void nn_kernel(const float* __restrict__ x,
                                                 const float* __restrict__ w1,
                                                 const float* __restrict__ b1,
                                                 const float* __restrict__ b2,
                                                 int B) {
    __shared__ float s_h[8 * 1024];   // [r][h]
    __shared__ float s_f[8][5];

    int b0  = blockIdx.x * 8;
    int tid = threadIdx.x;

    if (tid < 40) {
        int r = tid / 5, k = tid % 5;
        s_f[r][k] = x[(b0 + r) * 105 + k];
    }
    __syncthreads();

    for (int j = 0; j < 4; j++) {
        int h = tid + 256 * j;
        const float* wr = w1 + h * 5;
        float w0 = wr[0], w1v = wr[1], w2v = wr[2], w3 = wr[3], w4 = wr[4];
        float bb = b1[h];
        #pragma unroll
        for (int r = 0; r < 8; r++) {
            float v = bb + s_f[r][0] * w0 + s_f[r][1] * w1v + s_f[r][2] * w2v +
                      s_f[r][3] * w3 + s_f[r][4] * w4;
            s_h[r * 1024 + h] = v > 0.f ? v : 0.f;
        }
    }
    __syncthreads();

    int o  = tid & 63;
    int rg = tid >> 6;
    float a0 = 0.f, a1 = 0.f;
    const float* h0 = s_h + (rg * 2) * 1024;
    const float* h1 = s_h + (rg * 2 + 1) * 1024;
    for (int h = 0; h < 1024; h++) {
        float w = g_nnw2T[h * 64 + o];
        a0 += w * h0[h];
        a1 += w * h1[h];
    }
    float bo = b2[o];
    g_nn[(b0 + rg * 2) * 64 + o]     = a0 + bo;
    g_nn[(b0 + rg * 2 + 1) * 64 + o] = a1 + bo;
}

// ---------------- CNN: 16 rows/block, 512 thr (k-split), f32x2 FC ------------
#define CNN_SMEM_BYTES ((25600 + 16 * 102) * 4)

__global__ __launch_bounds__(512, 2) void cnn_kernel(const float* __restrict__ x,
                                                     const float* __restrict__ cw,
                                                     const float* __restrict__ cb,
                                                     const float* __restrict__ fcb,
                                                     int B) {
    extern __shared__ float sm[];
    float* s_p    = sm;            // pooled, transposed: [k=ch*50+j][r] (1600 x 16)
    float* s_wave = sm + 25600;    // [r][102] zero-padded

    __shared__ float s_cw[96];
    __shared__ float s_cb[32];

    int b0  = blockIdx.x * 16;
    int tid = threadIdx.x;

    if (tid < 96) s_cw[tid] = cw[tid];
    if (tid < 32) s_cb[tid] = cb[tid];
    for (int i = tid; i < 16 * 102; i += 512) {
        int r = i / 102, q = i % 102;
        float v = 0.f;
        if (q >= 1 && q <= 100) v = x[(b0 + r) * 105 + 4 + q];
        s_wave[i] = v;
    }
    __syncthreads();

    for (int i = tid; i < 25600; i += 512) {
        int r   = i & 15;
        int pos = i >> 4;
        int ch  = pos / 50;
        int j   = pos - ch * 50;
        const float* wv = s_wave + r * 102 + 2 * j;
        float w0 = s_cw[ch * 3], w1 = s_cw[ch * 3 + 1], w2 = s_cw[ch * 3 + 2];
        float bb = s_cb[ch];
        float c0 = bb + wv[0] * w0 + wv[1] * w1 + wv[2] * w2;
        float c1 = bb + wv[1] * w0 + wv[2] * w1 + wv[3] * w2;
        float m = fmaxf(c0, c1);
        s_p[pos * 16 + r] = m > 0.f ? m : 0.f;
    }
    __syncthreads();

    int o  = tid & 255;
    int kh = tid >> 8;
    unsigned long long a[8];
    #pragma unroll
    for (int q = 0; q < 8; q++) a[q] = 0ull;

    int kbeg = kh * 800;
    const float* fp = g_fcT + (size_t)kbeg * 256 + o;
    const ulonglong2* rp = (const ulonglong2*)s_p + kbeg * 4;

    for (int kk = 0; kk < 800; kk += 4) {
        float w0 = fp[0], w1 = fp[256], w2 = fp[512], w3 = fp[768];
        fp += 1024;
        unsigned long long W[4];
        asm("mov.b64 %0, {%1, %1};" : "=l"(W[0]) : "r"(__float_as_uint(w0)));
        asm("mov.b64 %0, {%1, %1};" : "=l"(W[1]) : "r"(__float_as_uint(w1)));
        asm("mov.b64 %0, {%1, %1};" : "=l"(W[2]) : "r"(__float_as_uint(w2)));
        asm("mov.b64 %0, {%1, %1};" : "=l"(W[3]) : "r"(__float_as_uint(w3)));
        #pragma unroll
        for (int u = 0; u < 4; u++) {
            #pragma unroll
            for (int m2 = 0; m2 < 4; m2++) {
                ulonglong2 v = rp[u * 4 + m2];
                asm("fma.rn.f32x2 %0, %1, %2, %0;" : "+l"(a[2 * m2])     : "l"(v.x), "l"(W[u]));
                asm("fma.rn.f32x2 %0, %1, %2, %0;" : "+l"(a[2 * m2 + 1]) : "l"(v.y), "l"(W[u]));
            }
        }
        rp += 16;
    }

    if (kh == 1) {
        #pragma unroll
        for (int q = 0; q < 8; q++) {
            float lo = __uint_as_float((unsigned)(a[q] & 0xffffffffull));
            float hi = __uint_as_float((unsigned)(a[q] >> 32));
            g_cnn[(b0 + 2 * q) * 256 + o]     = lo;
            g_cnn[(b0 + 2 * q + 1) * 256 + o] = hi;
        }
    }
    __syncthreads();
    if (kh == 0) {
        float fb = fcb[o];
        #pragma unroll
        for (int q = 0; q < 8; q++) {
            float lo = __uint_as_float((unsigned)(a[q] & 0xffffffffull));
            float hi = __uint_as_float((unsigned)(a[q] >> 32));
            int r0 = (b0 + 2 * q) * 256 + o;
            int r1 = (b0 + 2 * q + 1) * 256 + o;
            g_cnn[r0] = lo + fb + g_cnn[r0];
            g_cnn[r1] = hi + fb + g_cnn[r1];
        }
    }
}

// ---------------- combiner ----------------------------------------------------
__global__ __launch_bounds__(256) void comb_kernel(const float* __restrict__ cbias,
                                                   float* __restrict__ out,
                                                   int B) {
    __shared__ float s_c[16 * 384];   // [r][c]
    int b0  = blockIdx.x * 16;
    int tid = threadIdx.x;

    for (int i = tid; i < 16 * 64; i += 256) {
        int r = i >> 6, o = i & 63;
        s_c[r * 384 + o]      = g_snn[(b0 + r) * 64 + o];
        s_c[r * 384 + 64 + o] = g_nn[(b0 + r) * 64 + o];
    }
    for (int i = tid; i < 16 * 256; i += 256) {
        int r = i >> 8, o = i & 255;
        s_c[r * 384 + 128 + o] = g_cnn[(b0 + r) * 256 + o];
    }
    __syncthreads();

    int o  = tid & 63;
    int rg = tid >> 6;
    float a[4] = {0.f, 0.f, 0.f, 0.f};
    for (int c = 0; c < 384; c++) {
        float w = g_combT[c * 64 + o];
        const float* pr = s_c + (rg * 4) * 384 + c;
        a[0] += w * pr[0];
        a[1] += w * pr[384];
        a[2] += w * pr[2 * 384];
        a[3] += w * pr[3 * 384];
    }
    float bo = cbias[o];
    #pragma unroll
    for (int q = 0; q < 4; q++)
        out[(b0 + rg * 4 + q) * 64 + o] = a[q] + bo;
}

// ---------------- launch -------------------------------------------------------
extern "C" void kernel_launch(void* const* d_in, const int* in_sizes, int n_in,
                              void* d_out, int out_size) {
    const float* x      = (const float*)d_in[0];
    const float* snn_w1 = (const float*)d_in[1];
    const float* snn_b1 = (const float*)d_in[2];
    const float* snn_w2 = (const float*)d_in[3];
    const float* snn_b2 = (const float*)d_in[4];
    const float* nn_w1  = (const float*)d_in[5];
    const float* nn_b1  = (const float*)d_in[6];
    const float* nn_w2  = (const float*)d_in[7];
    const float* nn_b2  = (const float*)d_in[8];
    const float* conv_w = (const float*)d_in[9];
    const float* conv_b = (const float*)d_in[10];
    const float* fc_w   = (const float*)d_in[11];
    const float* fc_b   = (const float*)d_in[12];
    const float* comb_w = (const float*)d_in[13];
    const float* comb_b = (const float*)d_in[14];

    int B = in_sizes[0] / 105;

    cudaFuncSetAttribute(cnn_kernel, cudaFuncAttributeMaxDynamicSharedMemorySize,
                         CNN_SMEM_BYTES);

    prep_kernel<<<1600, 256>>>(snn_w2, nn_w2, fc_w, comb_w);
    snn_kernel<<<B, 1024>>>(x, snn_w1, snn_b1, snn_b2, B);
    nn_kernel<<<B / 8, 256>>>(x, nn_w1, nn_b1, nn_b2, B);
    cnn_kernel<<<B / 16, 512, CNN_SMEM_BYTES>>>(x, conv_w, conv_b, fc_b, B);
    comb_kernel<<<B / 16, 256>>>(comb_b, (float*)d_out, B);
}